// round 11
// baseline (speedup 1.0000x reference)
#include <cuda_runtime.h>
#include <cuda_bf16.h>
#include <cuda_fp16.h>
#include <math_constants.h>
#include <cstdint>

// Problem dims
#define BB 4
#define SS 4096
#define DD 768
#define RR (BB*SS)        // 16384
#define FF 385            // rfft bins
// Layouts
#define SLOT    772
#define MROWS   2432
#define GS_ROWS 2440
#define K3      2304      // fold K (bf16 3-term)
#define KA3     1536      // stage-3 A row len (fp16 hi|lo)
#define KB3     768       // stage-3 B row len (fp16 hi)
#define KA5     1664      // stage-5 A row len (fp16 hi|lo)
#define KB5     832       // stage-5 B row len (fp16 hi)
#define TWROWS  896
#define SCALE5  (1.0f/4096.0f)
#define ISCALE5 4096.0f

// ---------------- scratch ----------------
__device__ __nv_bfloat16 d_TwS[TWROWS * K3];
__device__ __nv_bfloat16 d_Ws [3 * DD * K3];
__device__ __half        d_Gs [GS_ROWS * KA3];
__device__ __half        d_Xs [(size_t)RR * KB3];
__device__ float         d_XFt[(size_t)MROWS * RR];
__device__ __half        d_OFs[(size_t)RR * KA5];
__device__ __half        d_ITb[DD * KB5];

// ---------------- helpers ----------------
__device__ __forceinline__ uint32_t s2u(const void* p) {
    uint32_t a;
    asm("{ .reg .u64 t; cvta.to.shared.u64 t, %1; cvt.u32.u64 %0, t; }" : "=r"(a) : "l"(p));
    return a;
}
__device__ __forceinline__ uint32_t swz(uint32_t o) { return o ^ ((o >> 3) & 0x70); }
#define CP16(dst, src) asm volatile("cp.async.cg.shared.global [%0], [%1], 16;" :: "r"(dst), "l"(src))
#define CP_COMMIT()    asm volatile("cp.async.commit_group;" ::: "memory")
#define WG(n) asm volatile("cp.async.wait_group " #n ";" ::: "memory")

__device__ __forceinline__ uint32_t packh(__half a, __half b) {
    return (uint32_t)__half_as_ushort(a) | ((uint32_t)__half_as_ushort(b) << 16);
}
__device__ __forceinline__ uint32_t packsplit_h(float v0, float v1, uint32_t& lo) {
    __half h0 = __float2half(v0); __half l0 = __float2half(v0 - __half2float(h0));
    __half h1 = __float2half(v1); __half l1 = __float2half(v1 - __half2float(h1));
    lo = packh(l0, l1);
    return packh(h0, h1);
}
__device__ __forceinline__ void split2b(float v, __nv_bfloat16& h, __nv_bfloat16& l) {
    h = __float2bfloat16(v);
    l = __float2bfloat16(v - __bfloat162float(h));
}
__device__ __forceinline__ uint32_t packbf(__nv_bfloat16 a, __nv_bfloat16 b) {
    return (uint32_t)__bfloat16_as_ushort(a) | ((uint32_t)__bfloat16_as_ushort(b) << 16);
}
__device__ __forceinline__ uint32_t packsplit_b(float v0, float v1, uint32_t& lo) {
    __nv_bfloat16 h0, l0, h1, l1; split2b(v0, h0, l0); split2b(v1, h1, l1);
    lo = packbf(l0, l1);
    return packbf(h0, h1);
}

template <bool BF>
__device__ __forceinline__ void mma16816(float* d, const uint32_t* a, uint32_t b0, uint32_t b1) {
    if constexpr (BF)
        asm volatile(
            "mma.sync.aligned.m16n8k16.row.col.f32.bf16.bf16.f32 "
            "{%0,%1,%2,%3}, {%4,%5,%6,%7}, {%8,%9}, {%0,%1,%2,%3};"
            : "+f"(d[0]), "+f"(d[1]), "+f"(d[2]), "+f"(d[3])
            : "r"(a[0]), "r"(a[1]), "r"(a[2]), "r"(a[3]), "r"(b0), "r"(b1));
    else
        asm volatile(
            "mma.sync.aligned.m16n8k16.row.col.f32.f16.f16.f32 "
            "{%0,%1,%2,%3}, {%4,%5,%6,%7}, {%8,%9}, {%0,%1,%2,%3};"
            : "+f"(d[0]), "+f"(d[1]), "+f"(d[2]), "+f"(d[3])
            : "r"(a[0]), "r"(a[1]), "r"(a[2]), "r"(a[3]), "r"(b0), "r"(b1));
}

// ---------------- fused prep: TwS + ITb tables, W^T split, X convert ----------------
__global__ void prep_kernel(const float* __restrict__ x,
                            const float* __restrict__ Wk, const float* __restrict__ Wv,
                            const float* __restrict__ Wq) {
    const int idx = blockIdx.x * blockDim.x + threadIdx.x;
    const float w = 2.0f * CUDART_PI_F / (float)DD;

    // TwS (fold A, bf16 3-term)
    if (idx < TWROWS * (DD / 2)) {
        int c = idx / (DD / 2), op = idx % (DD / 2);
        float v0 = 0.0f, v1 = 0.0f;
        if (c < 2 * FF) {
            int f = (c < FF) ? c : (c - FF);
            int r0 = (f * (2 * op)) % DD, r1 = (f * (2 * op + 1)) % DD;
            if (c < FF) { v0 = cosf(w * (float)r0);  v1 = cosf(w * (float)r1); }
            else        { v0 = -sinf(w * (float)r0); v1 = -sinf(w * (float)r1); }
        }
        uint32_t lp, hp = packsplit_b(v0, v1, lp);
        uint32_t* row = (uint32_t*)(d_TwS + (size_t)c * K3);
        row[op] = hp; row[DD / 2 + op] = lp; row[DD + op] = hp;     // (hi, lo, hi)
    }
    // ITb (stage-5 B, fp16 hi)
    if (idx < DD * (KB5 / 2)) {
        int d = idx / (KB5 / 2), fp = idx % (KB5 / 2);
        float v0 = 0.0f, v1 = 0.0f;
        if (fp < FF) {
            int f = fp;
            bool edge = (f == 0) || (f == DD / 2);
            float c = edge ? (1.0f / DD) : (2.0f / DD);
            int r = (f * d) % DD;
            float ang = w * (float)r;
            v0 = c * cosf(ang);
            v1 = edge ? 0.0f : -c * sinf(ang);
        }
        uint32_t* row = (uint32_t*)(d_ITb + (size_t)d * KB5);
        row[fp] = packh(__float2half(v0), __float2half(v1));
    }
    // W^T split (fold B, bf16 3-term)
    if (idx < 3 * (DD / 2) * DD) {
        int z = idx / ((DD / 2) * DD);
        int rem = idx % ((DD / 2) * DD);
        int op = rem / DD, in = rem % DD;
        const float* W = (z == 0) ? Wk : (z == 1) ? Wv : Wq;
        float v0 = W[(size_t)(2 * op) * DD + in];
        float v1 = W[(size_t)(2 * op + 1) * DD + in];
        uint32_t lp, hp = packsplit_b(v0, v1, lp);
        uint32_t* row = (uint32_t*)(d_Ws + (size_t)(z * DD + in) * K3);
        row[op] = hp; row[DD / 2 + op] = hp; row[DD + op] = lp;     // (hi, hi, lo)
    }
    // X convert (stage-3 B, fp16 hi)
    if (idx < RR * DD / 2) {
        int r = idx / (DD / 2), cp = idx % (DD / 2);
        float2 v = *(const float2*)&x[(size_t)r * DD + cp * 2];
        ((uint32_t*)(d_Xs + (size_t)r * KB3))[cp] = packh(__float2half(v.x), __float2half(v.y));
    }
}

// ---------------- HMMA GEMM: C[m,n] = sum_k A[m,k]*B[n,k] ----------------
// CTA tile 128xNT, 8 warps (2m x 4n), warp tile 64x(NT/4), BK=64.
// A ring of 4 stages; B ring of (REUSE ? 3 : 4) buffers.
// REUSE=1: virtual chunk kt -> A chunk (kt&1 ? kt/2+NKT/2 : kt/2), B chunk kt>>1
//          (each B chunk loaded ONCE, consumed by A-hi and A-lo passes; B loads
//           only on even groups, so ring-3 is race-free at prefetch depth 3).
// REUSE=0 (fold): A chunk kt, B chunk kt; B ring MUST be 4-deep (prefetch depth
//          3 writes slot kt%3 during compute(kt) otherwise).
// MODE 0: fp32 C.  MODE 1: C = resid + gain[0]*4096*acc.
// MODE 2 (fold, bf16): fp16-split store into d_Gs (+z slot), masked col<SLOT.
template <int MODE, int NT, int REUSE>
__global__ __launch_bounds__(256, 1) void hmma_gemm(
    int NKT,
    const __nv_bfloat16* __restrict__ A, int lda,
    const __nv_bfloat16* __restrict__ B, int ldb,
    float* __restrict__ C, int ldc,
    const float* __restrict__ resid, const float* __restrict__ gain)
{
    constexpr int NFR = NT / 32;                 // n-frags per warp
    constexpr int BRING = REUSE ? 3 : 4;
    constexpr uint32_t ASZ = 16384u;
    constexpr uint32_t BSZ = (uint32_t)NT * 128u;

    extern __shared__ char smraw[];
    const uint32_t sbase = (s2u(smraw) + 1023u) & ~1023u;
    const uint32_t bbase = sbase + 4u * ASZ;
    const int t = threadIdx.x;
    const int lane = t & 31, w = t >> 5;
    const int wm = w >> 2, wn = w & 3;
    const int m0 = blockIdx.x * 128, n0 = blockIdx.y * NT;
    if (MODE == 2) B += (size_t)blockIdx.z * DD * ldb;
    const int BPER = REUSE ? (NKT >> 1) : NKT;

    float acc[4][NFR][4];
#pragma unroll
    for (int i = 0; i < 4; i++)
#pragma unroll
        for (int j = 0; j < NFR; j++)
#pragma unroll
            for (int q = 0; q < 4; q++) acc[i][j][q] = 0.0f;

    const int arow = wm * 64 + (lane & 15);
    const int akoff = (lane >> 4) * 16;
    const int brow0 = (lane & 7) + ((lane >> 4) * 8);
    const int bkoff = ((lane >> 3) & 1) * 16;

    auto issue = [&](int kt) {
        const uint32_t sA = sbase + (uint32_t)(kt & 3) * ASZ;
        const int akt = REUSE ? ((kt & 1) ? (kt >> 1) + BPER : (kt >> 1)) : kt;
#pragma unroll
        for (int i = 0; i < 4; i++) {
            const int s = t + i * 256, row = s >> 3, c = s & 7;
            CP16(sA + swz((uint32_t)(row * 128 + c * 16)),
                 (const char*)A + ((size_t)(m0 + row) * lda + akt * 64 + c * 8) * 2);
        }
        if (!REUSE || !(kt & 1)) {
            const int bkt = REUSE ? (kt >> 1) : kt;
            const uint32_t sB = bbase + (uint32_t)(bkt % BRING) * BSZ;
#pragma unroll
            for (int i = 0; i < NT / 32; i++) {
                const int s = t + i * 256, row = s >> 3, c = s & 7;
                CP16(sB + swz((uint32_t)(row * 128 + c * 16)),
                     (const char*)B + ((size_t)(n0 + row) * ldb + bkt * 64 + c * 8) * 2);
            }
        }
        CP_COMMIT();
    };

    issue(0);
    if (NKT > 1) issue(1);
    if (NKT > 2) issue(2);
    for (int kt = 0; kt < NKT; kt++) {
        const int rem = NKT - kt - 1;
        if (rem >= 2)      { WG(2); }
        else if (rem == 1) { WG(1); }
        else               { WG(0); }
        __syncthreads();
        if (kt + 3 < NKT) issue(kt + 3);

        const uint32_t sA = sbase + (uint32_t)(kt & 3) * ASZ;
        const uint32_t sB = bbase + (uint32_t)((REUSE ? (kt >> 1) : kt) % BRING) * BSZ;
#pragma unroll
        for (int k16 = 0; k16 < 4; k16++) {
            uint32_t a[4][4];
#pragma unroll
            for (int mf = 0; mf < 4; mf++) {
                uint32_t addr = sA + swz((uint32_t)((arow + mf * 16) * 128 + k16 * 32 + akoff));
                asm volatile("ldmatrix.sync.aligned.m8n8.x4.shared.b16 {%0,%1,%2,%3}, [%4];"
                    : "=r"(a[mf][0]), "=r"(a[mf][1]), "=r"(a[mf][2]), "=r"(a[mf][3]) : "r"(addr));
            }
#pragma unroll
            for (int p = 0; p < NT / 64; p++) {
                uint32_t q0, q1, q2, q3;
                uint32_t addr = sB + swz((uint32_t)((wn * (NT / 4) + p * 16 + brow0) * 128 + k16 * 32 + bkoff));
                asm volatile("ldmatrix.sync.aligned.m8n8.x4.shared.b16 {%0,%1,%2,%3}, [%4];"
                    : "=r"(q0), "=r"(q1), "=r"(q2), "=r"(q3) : "r"(addr));
#pragma unroll
                for (int mf = 0; mf < 4; mf++) {
                    mma16816<MODE == 2>(acc[mf][2 * p], a[mf], q0, q1);
                    mma16816<MODE == 2>(acc[mf][2 * p + 1], a[mf], q2, q3);
                }
            }
        }
    }

    // ---------------- epilogue ----------------
    const int r = lane >> 2, c2 = (lane & 3) * 2;
    if (MODE == 2) {
        __half* gbase = d_Gs + (size_t)blockIdx.z * SLOT * KA3;
#pragma unroll
        for (int mf = 0; mf < 4; mf++) {
#pragma unroll
            for (int nf = 0; nf < NFR; nf++) {
                const int ml = m0 + wm * 64 + mf * 16 + r;
                const int n = n0 + wn * (NT / 4) + nf * 8 + c2;
#pragma unroll
                for (int hh = 0; hh < 2; hh++) {
                    const int mrow = ml + hh * 8;
                    if (mrow < SLOT) {
                        uint32_t lp, hp = packsplit_h(acc[mf][nf][2 * hh], acc[mf][nf][2 * hh + 1], lp);
                        uint32_t* orow = (uint32_t*)(gbase + (size_t)mrow * KA3);
                        orow[n / 2] = hp; orow[KB3 / 2 + n / 2] = lp;   // (hi | lo)
                    }
                }
            }
        }
        return;
    }
    const float g = (MODE == 1) ? gain[0] * ISCALE5 : 0.0f;
#pragma unroll
    for (int mf = 0; mf < 4; mf++) {
#pragma unroll
        for (int nf = 0; nf < NFR; nf++) {
            const int m = m0 + wm * 64 + mf * 16 + r;
            const int n = n0 + wn * (NT / 4) + nf * 8 + c2;
            const size_t o0 = (size_t)m * ldc + n;
            const size_t o1 = (size_t)(m + 8) * ldc + n;
            if (MODE == 1) {
                float2 x0 = *(const float2*)&resid[o0];
                float2 x1 = *(const float2*)&resid[o1];
                *(float2*)&C[o0] = make_float2(x0.x + g * acc[mf][nf][0], x0.y + g * acc[mf][nf][1]);
                *(float2*)&C[o1] = make_float2(x1.x + g * acc[mf][nf][2], x1.y + g * acc[mf][nf][3]);
            } else {
                *(float2*)&C[o0] = make_float2(acc[mf][nf][0], acc[mf][nf][1]);
                *(float2*)&C[o1] = make_float2(acc[mf][nf][2], acc[mf][nf][3]);
            }
        }
    }
}

// ---------------- causal scan (shuffle-based), fused fp16-split + 2^-12 prescale ----------------
__global__ __launch_bounds__(512) void scan_kernel() {
    const int f = blockIdx.x;
    const int b = blockIdx.y;
    const int base = b * SS;
    const int t = threadIdx.x;
    const int lane = t & 31, wid = t >> 5;
    const int s0 = t * 8;

    const float* kre = d_XFt + (size_t)(0 * SLOT + f)      * RR + base;
    const float* kim = d_XFt + (size_t)(0 * SLOT + FF + f) * RR + base;
    const float* vre = d_XFt + (size_t)(1 * SLOT + f)      * RR + base;
    const float* vim = d_XFt + (size_t)(1 * SLOT + FF + f) * RR + base;
    const float* qre = d_XFt + (size_t)(2 * SLOT + f)      * RR + base;
    const float* qim = d_XFt + (size_t)(2 * SLOT + FF + f) * RR + base;

    float kr[8], ki[8], vr[8], vi[8], qr[8], qi[8];
#pragma unroll
    for (int h = 0; h < 2; h++) {
        *(float4*)(kr + 4 * h) = *(const float4*)(kre + s0 + 4 * h);
        *(float4*)(ki + 4 * h) = *(const float4*)(kim + s0 + 4 * h);
        *(float4*)(vr + 4 * h) = *(const float4*)(vre + s0 + 4 * h);
        *(float4*)(vi + 4 * h) = *(const float4*)(vim + s0 + 4 * h);
        *(float4*)(qr + 4 * h) = *(const float4*)(qre + s0 + 4 * h);
        *(float4*)(qi + 4 * h) = *(const float4*)(qim + s0 + 4 * h);
    }

    float lr[8], li[8], runr = 0.0f, runi = 0.0f;
#pragma unroll
    for (int i = 0; i < 8; i++) {
        float zr = kr[i] * vr[i] - ki[i] * vi[i];
        float zi = kr[i] * vi[i] + ki[i] * vr[i];
        runr += zr; runi += zi;
        lr[i] = runr; li[i] = runi;
    }

    float wr = runr, wi = runi;
#pragma unroll
    for (int off = 1; off < 32; off <<= 1) {
        float pr = __shfl_up_sync(0xFFFFFFFFu, wr, off);
        float pi = __shfl_up_sync(0xFFFFFFFFu, wi, off);
        if (lane >= off) { wr += pr; wi += pi; }
    }
    __shared__ float swr[16], swi[16];
    if (lane == 31) { swr[wid] = wr; swi[wid] = wi; }
    __syncthreads();
    if (t < 32) {
        float vr2 = (t < 16) ? swr[t] : 0.0f;
        float vi2 = (t < 16) ? swi[t] : 0.0f;
#pragma unroll
        for (int off = 1; off < 16; off <<= 1) {
            float pr = __shfl_up_sync(0xFFFFFFFFu, vr2, off);
            float pi = __shfl_up_sync(0xFFFFFFFFu, vi2, off);
            if (lane >= off) { vr2 += pr; vi2 += pi; }
        }
        if (t < 16) { swr[t] = vr2; swi[t] = vi2; }
    }
    __syncthreads();
    const float baser = (wid > 0) ? swr[wid - 1] : 0.0f;
    const float basei = (wid > 0) ? swi[wid - 1] : 0.0f;
    const float exr = baser + (wr - runr);
    const float exi = basei + (wi - runi);

#pragma unroll
    for (int i = 0; i < 8; i++) {
        float mr = exr + lr[i];
        float mi = exi + li[i];
        float ox = (mr * qr[i] + mi * qi[i]) * SCALE5;   // Re -> j=2f
        float oy = (mi * qr[i] - mr * qi[i]) * SCALE5;   // Im -> j=2f+1
        uint32_t lp, hp = packsplit_h(ox, oy, lp);
        uint32_t* orow = (uint32_t*)(d_OFs + (size_t)(base + s0 + i) * KA5);
        orow[f] = hp; orow[KB5 / 2 + f] = lp;            // (hi | lo)
    }
}

// ---------------- launch ----------------
#define SMEM_BIG  (4 * 16384 + 3 * 256 * 128 + 1024)     // A ring 4 + B ring 3 (NT=256)
#define SMEM_FOLD (4 * 16384 + 4 * 128 * 128 + 1024)     // A ring 4 + B ring 4 (NT=128 fold)
extern "C" void kernel_launch(void* const* d_in, const int* in_sizes, int n_in,
                              void* d_out, int out_size) {
    const float* x    = (const float*)d_in[0];
    const float* Wk   = (const float*)d_in[1];
    const float* Wv   = (const float*)d_in[2];
    const float* Wq   = (const float*)d_in[3];
    const float* gain = (const float*)d_in[4];
    float* out = (float*)d_out;

    void *pTwS, *pWs, *pGs, *pXs, *pOFs, *pITb, *pXFt;
    cudaGetSymbolAddress(&pTwS, d_TwS);
    cudaGetSymbolAddress(&pWs,  d_Ws);
    cudaGetSymbolAddress(&pGs,  d_Gs);
    cudaGetSymbolAddress(&pXs,  d_Xs);
    cudaGetSymbolAddress(&pOFs, d_OFs);
    cudaGetSymbolAddress(&pITb, d_ITb);
    cudaGetSymbolAddress(&pXFt, d_XFt);

    cudaFuncSetAttribute((const void*)hmma_gemm<0, 256, 1>, cudaFuncAttributeMaxDynamicSharedMemorySize, SMEM_BIG);
    cudaFuncSetAttribute((const void*)hmma_gemm<1, 256, 1>, cudaFuncAttributeMaxDynamicSharedMemorySize, SMEM_BIG);
    cudaFuncSetAttribute((const void*)hmma_gemm<2, 128, 0>, cudaFuncAttributeMaxDynamicSharedMemorySize, SMEM_FOLD);

    // 0) fused prep: tables + W split + X convert (one launch)
    prep_kernel<<<(RR * DD / 2 + 255) / 256, 256>>>(x, Wk, Wv, Wq);

    // 1) fold GEMM (bf16 3-term, NT=128, fp16-split store into Gs)
    hmma_gemm<2, 128, 0><<<dim3(TWROWS / 128, DD / 128, 3), 256, SMEM_FOLD>>>(
        K3 / 64,
        (const __nv_bfloat16*)pTwS, K3, (const __nv_bfloat16*)pWs, K3,
        nullptr, 0, nullptr, nullptr);

    // 2) stage-3 GEMM (fp16 2-term, B loaded once per chunk-pair):
    //    XFt[col, r]  M=2432, N=16384, K=1536 (24 virtual chunks, 12 B chunks)
    hmma_gemm<0, 256, 1><<<dim3(MROWS / 128, RR / 256), 256, SMEM_BIG>>>(
        KA3 / 64,
        (const __nv_bfloat16*)pGs, KA3, (const __nv_bfloat16*)pXs, KB3,
        (float*)pXFt, RR, nullptr, nullptr);

    // 3) causal scan -> OFs (fp16 split + prescale, fused)
    scan_kernel<<<dim3(FF, BB), 512>>>();

    // 4) stage-5 GEMM + residual (fp16 2-term, B reuse): out[r,d]  M=16384, N=768, K=1664
    hmma_gemm<1, 256, 1><<<dim3(RR / 128, DD / 256), 256, SMEM_BIG>>>(
        KA5 / 64,
        (const __nv_bfloat16*)pOFs, KA5, (const __nv_bfloat16*)pITb, KB5,
        out, DD, x, gain);
}

// round 14
// speedup vs baseline: 1.5979x; 1.5979x over previous
#include <cuda_runtime.h>
#include <cuda_bf16.h>
#include <cuda_fp16.h>
#include <math_constants.h>
#include <cstdint>

// Problem dims
#define BB 4
#define SS 4096
#define DD 768
#define RR (BB*SS)        // 16384
#define FF 385            // rfft bins
// Layouts
#define SLOT    772
#define MROWS   2432
#define GS_ROWS 2440
#define K3      2304      // fold K (bf16 3-term)
#define KA3     1536      // stage-3 A row len (fp16 hi|lo)
#define KB3     768       // stage-3 B row len (fp16 hi)
#define KA5     1664      // stage-5 A rows (K-major: hi rows [0,832), lo rows [832,1664))
#define KB5     832       // stage-5 B row len (fp16 hi)
#define TWROWS  896
#define SCALE5  (1.0f/4096.0f)
#define ISCALE5 4096.0f

// ---------------- scratch ----------------
__device__ __nv_bfloat16 d_TwS[TWROWS * K3];
__device__ __nv_bfloat16 d_Ws [3 * DD * K3];
__device__ __half        d_Gs [GS_ROWS * KA3];
__device__ __half        d_Xs [(size_t)RR * KB3];
__device__ float         d_XFt[(size_t)MROWS * RR];
__device__ __half        d_OFsT[(size_t)KA5 * RR];       // stage-5 A, K-major [j, r]
__device__ __half        d_ITb[DD * KB5];

// ---------------- helpers ----------------
__device__ __forceinline__ uint32_t s2u(const void* p) {
    uint32_t a;
    asm("{ .reg .u64 t; cvta.to.shared.u64 t, %1; cvt.u32.u64 %0, t; }" : "=r"(a) : "l"(p));
    return a;
}
__device__ __forceinline__ uint32_t swz(uint32_t o) { return o ^ ((o >> 3) & 0x70); }
#define CP16(dst, src) asm volatile("cp.async.cg.shared.global [%0], [%1], 16;" :: "r"(dst), "l"(src))
#define CP_COMMIT()    asm volatile("cp.async.commit_group;" ::: "memory")
#define WG(n) asm volatile("cp.async.wait_group " #n ";" ::: "memory")

__device__ __forceinline__ uint32_t packh(__half a, __half b) {
    return (uint32_t)__half_as_ushort(a) | ((uint32_t)__half_as_ushort(b) << 16);
}
__device__ __forceinline__ uint32_t packsplit_h(float v0, float v1, uint32_t& lo) {
    __half h0 = __float2half(v0); __half l0 = __float2half(v0 - __half2float(h0));
    __half h1 = __float2half(v1); __half l1 = __float2half(v1 - __half2float(h1));
    lo = packh(l0, l1);
    return packh(h0, h1);
}
__device__ __forceinline__ void split2b(float v, __nv_bfloat16& h, __nv_bfloat16& l) {
    h = __float2bfloat16(v);
    l = __float2bfloat16(v - __bfloat162float(h));
}
__device__ __forceinline__ uint32_t packbf(__nv_bfloat16 a, __nv_bfloat16 b) {
    return (uint32_t)__bfloat16_as_ushort(a) | ((uint32_t)__bfloat16_as_ushort(b) << 16);
}
__device__ __forceinline__ uint32_t packsplit_b(float v0, float v1, uint32_t& lo) {
    __nv_bfloat16 h0, l0, h1, l1; split2b(v0, h0, l0); split2b(v1, h1, l1);
    lo = packbf(l0, l1);
    return packbf(h0, h1);
}

template <bool BF>
__device__ __forceinline__ void mma16816(float* d, const uint32_t* a, uint32_t b0, uint32_t b1) {
    if constexpr (BF)
        asm volatile(
            "mma.sync.aligned.m16n8k16.row.col.f32.bf16.bf16.f32 "
            "{%0,%1,%2,%3}, {%4,%5,%6,%7}, {%8,%9}, {%0,%1,%2,%3};"
            : "+f"(d[0]), "+f"(d[1]), "+f"(d[2]), "+f"(d[3])
            : "r"(a[0]), "r"(a[1]), "r"(a[2]), "r"(a[3]), "r"(b0), "r"(b1));
    else
        asm volatile(
            "mma.sync.aligned.m16n8k16.row.col.f32.f16.f16.f32 "
            "{%0,%1,%2,%3}, {%4,%5,%6,%7}, {%8,%9}, {%0,%1,%2,%3};"
            : "+f"(d[0]), "+f"(d[1]), "+f"(d[2]), "+f"(d[3])
            : "r"(a[0]), "r"(a[1]), "r"(a[2]), "r"(a[3]), "r"(b0), "r"(b1));
}

// ---------------- fused prep: TwS + ITb tables, W^T split, X convert ----------------
__global__ void prep_kernel(const float* __restrict__ x,
                            const float* __restrict__ Wk, const float* __restrict__ Wv,
                            const float* __restrict__ Wq) {
    const int idx = blockIdx.x * blockDim.x + threadIdx.x;
    const float w = 2.0f * CUDART_PI_F / (float)DD;

    if (idx < TWROWS * (DD / 2)) {
        int c = idx / (DD / 2), op = idx % (DD / 2);
        float v0 = 0.0f, v1 = 0.0f;
        if (c < 2 * FF) {
            int f = (c < FF) ? c : (c - FF);
            int r0 = (f * (2 * op)) % DD, r1 = (f * (2 * op + 1)) % DD;
            if (c < FF) { v0 = cosf(w * (float)r0);  v1 = cosf(w * (float)r1); }
            else        { v0 = -sinf(w * (float)r0); v1 = -sinf(w * (float)r1); }
        }
        uint32_t lp, hp = packsplit_b(v0, v1, lp);
        uint32_t* row = (uint32_t*)(d_TwS + (size_t)c * K3);
        row[op] = hp; row[DD / 2 + op] = lp; row[DD + op] = hp;     // (hi, lo, hi)
    }
    if (idx < DD * (KB5 / 2)) {
        int d = idx / (KB5 / 2), fp = idx % (KB5 / 2);
        float v0 = 0.0f, v1 = 0.0f;
        if (fp < FF) {
            int f = fp;
            bool edge = (f == 0) || (f == DD / 2);
            float c = edge ? (1.0f / DD) : (2.0f / DD);
            int r = (f * d) % DD;
            float ang = w * (float)r;
            v0 = c * cosf(ang);
            v1 = edge ? 0.0f : -c * sinf(ang);
        }
        uint32_t* row = (uint32_t*)(d_ITb + (size_t)d * KB5);
        row[fp] = packh(__float2half(v0), __float2half(v1));
    }
    if (idx < 3 * (DD / 2) * DD) {
        int z = idx / ((DD / 2) * DD);
        int rem = idx % ((DD / 2) * DD);
        int op = rem / DD, in = rem % DD;
        const float* W = (z == 0) ? Wk : (z == 1) ? Wv : Wq;
        float v0 = W[(size_t)(2 * op) * DD + in];
        float v1 = W[(size_t)(2 * op + 1) * DD + in];
        uint32_t lp, hp = packsplit_b(v0, v1, lp);
        uint32_t* row = (uint32_t*)(d_Ws + (size_t)(z * DD + in) * K3);
        row[op] = hp; row[DD / 2 + op] = hp; row[DD + op] = lp;     // (hi, hi, lo)
    }
    if (idx < RR * DD / 2) {
        int r = idx / (DD / 2), cp = idx % (DD / 2);
        float2 v = *(const float2*)&x[(size_t)r * DD + cp * 2];
        ((uint32_t*)(d_Xs + (size_t)r * KB3))[cp] = packh(__float2half(v.x), __float2half(v.y));
    }
}

// ---------------- HMMA GEMM: C[m,n] = sum_k A[m,k]*B[n,k] ----------------
// R8-proven loop: CTA tile 128xNT, 8 warps (2m x 4n), BK=64, 4-stage interleaved
// ring (A+B per stage), single barrier per chunk, B chunk wraps at BPER.
// ATRANS=1: A is K-major [k, m] (ld = elements per k-row); cp.async loads 64
//           k-rows x 128 m as 128 smem rows of 128B; A fragments via ldmatrix.trans.
// MODE 0: fp32 C.  MODE 1: C = resid + gain[0]*4096*acc.
// MODE 2 (fold, bf16): fp16-split store into d_Gs (+z slot), masked col<SLOT.
template <int MODE, int NT, int ATRANS>
__global__ __launch_bounds__(256, 1) void hmma_gemm(
    int NKT, int BPER,
    const __nv_bfloat16* __restrict__ A, int lda,
    const __nv_bfloat16* __restrict__ B, int ldb,
    float* __restrict__ C, int ldc,
    const float* __restrict__ resid, const float* __restrict__ gain)
{
    constexpr int NFR = NT / 32;
    constexpr uint32_t ASZ = 16384u;
    constexpr uint32_t BSZ = (uint32_t)NT * 128u;
    constexpr uint32_t STG = ASZ + BSZ;

    extern __shared__ char smraw[];
    const uint32_t sbase = (s2u(smraw) + 1023u) & ~1023u;
    const int t = threadIdx.x;
    const int lane = t & 31, w = t >> 5;
    const int wm = w >> 2, wn = w & 3;
    const int m0 = blockIdx.x * 128, n0 = blockIdx.y * NT;
    if (MODE == 2) B += (size_t)blockIdx.z * DD * ldb;

    float acc[4][NFR][4];
#pragma unroll
    for (int i = 0; i < 4; i++)
#pragma unroll
        for (int j = 0; j < NFR; j++)
#pragma unroll
            for (int q = 0; q < 4; q++) acc[i][j][q] = 0.0f;

    // non-trans A ldmatrix geometry
    const int arow = wm * 64 + (lane & 15);
    const int akoff = (lane >> 4) * 16;
    // trans A ldmatrix geometry (K-major smem tile, 128 rows x 128B)
    const int tkrow = (lane & 7) + ((lane >> 4) * 8);        // k within 16
    const int tcolb = ((lane >> 3) & 1) * 16;                // +8 halfs = 16B
    // B geometry
    const int brow0 = (lane & 7) + ((lane >> 4) * 8);
    const int bkoff = ((lane >> 3) & 1) * 16;

    auto issue = [&](int kt) {
        const uint32_t sA = sbase + (uint32_t)(kt & 3) * STG;
        const uint32_t sB = sA + ASZ;
        const int bkt = kt % BPER;
        if (ATRANS) {
#pragma unroll
            for (int i = 0; i < 4; i++) {
                const int s = t + i * 256;
                const int j = s >> 4, rseg = s & 15;
                const int smrow = j * 2 + (rseg >> 3);
                CP16(sA + swz((uint32_t)(smrow * 128 + (rseg & 7) * 16)),
                     (const char*)A + ((size_t)(kt * 64 + j) * lda + m0 + rseg * 8) * 2);
            }
        } else {
#pragma unroll
            for (int i = 0; i < 4; i++) {
                const int s = t + i * 256, row = s >> 3, c = s & 7;
                CP16(sA + swz((uint32_t)(row * 128 + c * 16)),
                     (const char*)A + ((size_t)(m0 + row) * lda + kt * 64 + c * 8) * 2);
            }
        }
#pragma unroll
        for (int i = 0; i < NT / 32; i++) {
            const int s = t + i * 256, row = s >> 3, c = s & 7;
            CP16(sB + swz((uint32_t)(row * 128 + c * 16)),
                 (const char*)B + ((size_t)(n0 + row) * ldb + bkt * 64 + c * 8) * 2);
        }
        CP_COMMIT();
    };

    issue(0);
    if (NKT > 1) issue(1);
    if (NKT > 2) issue(2);
    for (int kt = 0; kt < NKT; kt++) {
        const int rem = NKT - kt - 1;
        if (rem >= 2)      { WG(2); }
        else if (rem == 1) { WG(1); }
        else               { WG(0); }
        __syncthreads();
        if (kt + 3 < NKT) issue(kt + 3);

        const uint32_t sA = sbase + (uint32_t)(kt & 3) * STG;
        const uint32_t sB = sA + ASZ;
#pragma unroll
        for (int k16 = 0; k16 < 4; k16++) {
            uint32_t a[4][4];
            if (ATRANS) {
#pragma unroll
                for (int mf = 0; mf < 4; mf++) {
                    const int smrow = (k16 * 16 + tkrow) * 2 + wm;
                    uint32_t addr = sA + swz((uint32_t)(smrow * 128 + mf * 32 + tcolb));
                    asm volatile("ldmatrix.sync.aligned.m8n8.x4.trans.shared.b16 {%0,%1,%2,%3}, [%4];"
                        : "=r"(a[mf][0]), "=r"(a[mf][1]), "=r"(a[mf][2]), "=r"(a[mf][3]) : "r"(addr));
                }
            } else {
#pragma unroll
                for (int mf = 0; mf < 4; mf++) {
                    uint32_t addr = sA + swz((uint32_t)((arow + mf * 16) * 128 + k16 * 32 + akoff));
                    asm volatile("ldmatrix.sync.aligned.m8n8.x4.shared.b16 {%0,%1,%2,%3}, [%4];"
                        : "=r"(a[mf][0]), "=r"(a[mf][1]), "=r"(a[mf][2]), "=r"(a[mf][3]) : "r"(addr));
                }
            }
#pragma unroll
            for (int p = 0; p < NT / 64; p++) {
                uint32_t q0, q1, q2, q3;
                uint32_t addr = sB + swz((uint32_t)((wn * (NT / 4) + p * 16 + brow0) * 128 + k16 * 32 + bkoff));
                asm volatile("ldmatrix.sync.aligned.m8n8.x4.shared.b16 {%0,%1,%2,%3}, [%4];"
                    : "=r"(q0), "=r"(q1), "=r"(q2), "=r"(q3) : "r"(addr));
#pragma unroll
                for (int mf = 0; mf < 4; mf++) {
                    mma16816<MODE == 2>(acc[mf][2 * p], a[mf], q0, q1);
                    mma16816<MODE == 2>(acc[mf][2 * p + 1], a[mf], q2, q3);
                }
            }
        }
    }

    // ---------------- epilogue ----------------
    const int r = lane >> 2, c2 = (lane & 3) * 2;
    if (MODE == 2) {
        __half* gbase = d_Gs + (size_t)blockIdx.z * SLOT * KA3;
#pragma unroll
        for (int mf = 0; mf < 4; mf++) {
#pragma unroll
            for (int nf = 0; nf < NFR; nf++) {
                const int ml = m0 + wm * 64 + mf * 16 + r;
                const int n = n0 + wn * (NT / 4) + nf * 8 + c2;
#pragma unroll
                for (int hh = 0; hh < 2; hh++) {
                    const int mrow = ml + hh * 8;
                    if (mrow < SLOT) {
                        uint32_t lp, hp = packsplit_h(acc[mf][nf][2 * hh], acc[mf][nf][2 * hh + 1], lp);
                        uint32_t* orow = (uint32_t*)(gbase + (size_t)mrow * KA3);
                        orow[n / 2] = hp; orow[KB3 / 2 + n / 2] = lp;   // (hi | lo)
                    }
                }
            }
        }
        return;
    }
    const float g = (MODE == 1) ? gain[0] * ISCALE5 : 0.0f;
#pragma unroll
    for (int mf = 0; mf < 4; mf++) {
#pragma unroll
        for (int nf = 0; nf < NFR; nf++) {
            const int m = m0 + wm * 64 + mf * 16 + r;
            const int n = n0 + wn * (NT / 4) + nf * 8 + c2;
            const size_t o0 = (size_t)m * ldc + n;
            const size_t o1 = (size_t)(m + 8) * ldc + n;
            if (MODE == 1) {
                float2 x0 = *(const float2*)&resid[o0];
                float2 x1 = *(const float2*)&resid[o1];
                *(float2*)&C[o0] = make_float2(x0.x + g * acc[mf][nf][0], x0.y + g * acc[mf][nf][1]);
                *(float2*)&C[o1] = make_float2(x1.x + g * acc[mf][nf][2], x1.y + g * acc[mf][nf][3]);
            } else {
                *(float2*)&C[o0] = make_float2(acc[mf][nf][0], acc[mf][nf][1]);
                *(float2*)&C[o1] = make_float2(acc[mf][nf][2], acc[mf][nf][3]);
            }
        }
    }
}

// ---------------- causal scan: coalesced K-major fp16-split output ----------------
__global__ __launch_bounds__(512) void scan_kernel() {
    const int f = blockIdx.x;
    const int b = blockIdx.y;
    const int base = b * SS;
    const int t = threadIdx.x;
    const int lane = t & 31, wid = t >> 5;
    const int s0 = t * 8;

    const float* kre = d_XFt + (size_t)(0 * SLOT + f)      * RR + base;
    const float* kim = d_XFt + (size_t)(0 * SLOT + FF + f) * RR + base;
    const float* vre = d_XFt + (size_t)(1 * SLOT + f)      * RR + base;
    const float* vim = d_XFt + (size_t)(1 * SLOT + FF + f) * RR + base;
    const float* qre = d_XFt + (size_t)(2 * SLOT + f)      * RR + base;
    const float* qim = d_XFt + (size_t)(2 * SLOT + FF + f) * RR + base;

    float kr[8], ki[8], vr[8], vi[8], qr[8], qi[8];
#pragma unroll
    for (int h = 0; h < 2; h++) {
        *(float4*)(kr + 4 * h) = *(const float4*)(kre + s0 + 4 * h);
        *(float4*)(ki + 4 * h) = *(const float4*)(kim + s0 + 4 * h);
        *(float4*)(vr + 4 * h) = *(const float4*)(vre + s0 + 4 * h);
        *(float4*)(vi + 4 * h) = *(const float4*)(vim + s0 + 4 * h);
        *(float4*)(qr + 4 * h) = *(const float4*)(qre + s0 + 4 * h);
        *(float4*)(qi + 4 * h) = *(const float4*)(qim + s0 + 4 * h);
    }

    float lr[8], li[8], runr = 0.0f, runi = 0.0f;
#pragma unroll
    for (int i = 0; i < 8; i++) {
        float zr = kr[i] * vr[i] - ki[i] * vi[i];
        float zi = kr[i] * vi[i] + ki[i] * vr[i];
        runr += zr; runi += zi;
        lr[i] = runr; li[i] = runi;
    }

    float wr = runr, wi = runi;
#pragma unroll
    for (int off = 1; off < 32; off <<= 1) {
        float pr = __shfl_up_sync(0xFFFFFFFFu, wr, off);
        float pi = __shfl_up_sync(0xFFFFFFFFu, wi, off);
        if (lane >= off) { wr += pr; wi += pi; }
    }
    __shared__ float swr[16], swi[16];
    if (lane == 31) { swr[wid] = wr; swi[wid] = wi; }
    __syncthreads();
    if (t < 32) {
        float vr2 = (t < 16) ? swr[t] : 0.0f;
        float vi2 = (t < 16) ? swi[t] : 0.0f;
#pragma unroll
        for (int off = 1; off < 16; off <<= 1) {
            float pr = __shfl_up_sync(0xFFFFFFFFu, vr2, off);
            float pi = __shfl_up_sync(0xFFFFFFFFu, vi2, off);
            if (lane >= off) { vr2 += pr; vi2 += pi; }
        }
        if (t < 16) { swr[t] = vr2; swi[t] = vi2; }
    }
    __syncthreads();
    const float baser = (wid > 0) ? swr[wid - 1] : 0.0f;
    const float basei = (wid > 0) ? swi[wid - 1] : 0.0f;
    const float exr = baser + (wr - runr);
    const float exi = basei + (wi - runi);

    // compute + fp16-split into 4 coalesced 16B rows of OFsT
    uint32_t hx[4], lx[4], hy[4], ly[4];
#pragma unroll
    for (int i = 0; i < 4; i++) {
        float o0x, o0y, o1x, o1y;
        {
            float mr = exr + lr[2 * i],     mi = exi + li[2 * i];
            o0x = (mr * qr[2 * i] + mi * qi[2 * i]) * SCALE5;
            o0y = (mi * qr[2 * i] - mr * qi[2 * i]) * SCALE5;
        }
        {
            float mr = exr + lr[2 * i + 1], mi = exi + li[2 * i + 1];
            o1x = (mr * qr[2 * i + 1] + mi * qi[2 * i + 1]) * SCALE5;
            o1y = (mi * qr[2 * i + 1] - mr * qi[2 * i + 1]) * SCALE5;
        }
        uint32_t l0; hx[i] = packsplit_h(o0x, o1x, l0); lx[i] = l0;
        uint32_t l1; hy[i] = packsplit_h(o0y, o1y, l1); ly[i] = l1;
    }
    const size_t col = (size_t)base + s0;
    *(uint4*)&d_OFsT[(size_t)(2 * f)           * RR + col] = make_uint4(hx[0], hx[1], hx[2], hx[3]);
    *(uint4*)&d_OFsT[(size_t)(2 * f + 1)       * RR + col] = make_uint4(hy[0], hy[1], hy[2], hy[3]);
    *(uint4*)&d_OFsT[(size_t)(KB5 + 2 * f)     * RR + col] = make_uint4(lx[0], lx[1], lx[2], lx[3]);
    *(uint4*)&d_OFsT[(size_t)(KB5 + 2 * f + 1) * RR + col] = make_uint4(ly[0], ly[1], ly[2], ly[3]);
}

// ---------------- launch ----------------
#define SMEM_256 (4 * (16384 + 256 * 128) + 1024)
#define SMEM_128 (4 * (16384 + 128 * 128) + 1024)
extern "C" void kernel_launch(void* const* d_in, const int* in_sizes, int n_in,
                              void* d_out, int out_size) {
    const float* x    = (const float*)d_in[0];
    const float* Wk   = (const float*)d_in[1];
    const float* Wv   = (const float*)d_in[2];
    const float* Wq   = (const float*)d_in[3];
    const float* gain = (const float*)d_in[4];
    float* out = (float*)d_out;

    void *pTwS, *pWs, *pGs, *pXs, *pOFsT, *pITb, *pXFt;
    cudaGetSymbolAddress(&pTwS, d_TwS);
    cudaGetSymbolAddress(&pWs,  d_Ws);
    cudaGetSymbolAddress(&pGs,  d_Gs);
    cudaGetSymbolAddress(&pXs,  d_Xs);
    cudaGetSymbolAddress(&pOFsT, d_OFsT);
    cudaGetSymbolAddress(&pITb, d_ITb);
    cudaGetSymbolAddress(&pXFt, d_XFt);

    cudaFuncSetAttribute((const void*)hmma_gemm<0, 256, 0>, cudaFuncAttributeMaxDynamicSharedMemorySize, SMEM_256);
    cudaFuncSetAttribute((const void*)hmma_gemm<1, 256, 1>, cudaFuncAttributeMaxDynamicSharedMemorySize, SMEM_256);
    cudaFuncSetAttribute((const void*)hmma_gemm<2, 128, 0>, cudaFuncAttributeMaxDynamicSharedMemorySize, SMEM_128);

    // 0) fused prep: tables + W split + X convert
    prep_kernel<<<(RR * DD / 2 + 255) / 256, 256>>>(x, Wk, Wv, Wq);

    // 1) fold GEMM (bf16 3-term, NT=128, fp16-split store into Gs)
    hmma_gemm<2, 128, 0><<<dim3(TWROWS / 128, DD / 128, 3), 256, SMEM_128>>>(
        K3 / 64, K3 / 64,
        (const __nv_bfloat16*)pTwS, K3, (const __nv_bfloat16*)pWs, K3,
        nullptr, 0, nullptr, nullptr);

    // 2) stage-3 GEMM (fp16 2-term): XFt[col, r]  M=2432, N=16384, K=1536 (B period 768)
    hmma_gemm<0, 256, 0><<<dim3(MROWS / 128, RR / 256), 256, SMEM_256>>>(
        KA3 / 64, KB3 / 64,
        (const __nv_bfloat16*)pGs, KA3, (const __nv_bfloat16*)pXs, KB3,
        (float*)pXFt, RR, nullptr, nullptr);

    // 3) causal scan -> OFsT (K-major, coalesced fp16 split + prescale)
    scan_kernel<<<dim3(FF, BB), 512>>>();

    // 4) stage-5 GEMM + residual (fp16 2-term, A K-major via ldmatrix.trans):
    //    out[r,d]  M=16384, N=768, K=1664 (B period 832)
    hmma_gemm<1, 256, 1><<<dim3(RR / 128, DD / 256), 256, SMEM_256>>>(
        KA5 / 64, KB5 / 64,
        (const __nv_bfloat16*)pOFsT, RR, (const __nv_bfloat16*)pITb, KB5,
        out, DD, x, gain);
}

// round 17
// speedup vs baseline: 2.1317x; 1.3340x over previous
#include <cuda_runtime.h>
#include <cuda_bf16.h>
#include <cuda_fp16.h>
#include <math_constants.h>
#include <cstdint>

// Problem dims
#define BB 4
#define SS 4096
#define DD 768
#define RR (BB*SS)        // 16384
#define FF 385            // rfft bins
// Layouts
#define SLOT    772
#define MROWS   2432
#define GS_ROWS 2440
#define K3      2304      // fold K (bf16 3-term)
#define KA3     768       // stage-3 A row len (fp16 hi ONLY — 1-term)
#define KB3     768       // stage-3 B row len (fp16 hi)
#define KA5     1664      // stage-5 A rows (K-major: hi rows [0,832), lo rows [832,1664))
#define KB5     832       // stage-5 B row len (fp16 hi)
#define TWROWS  896
#define SCALE5  (1.0f/4096.0f)
#define ISCALE5 4096.0f

// ---------------- scratch ----------------
__device__ __nv_bfloat16 d_TwS[TWROWS * K3];
__device__ __nv_bfloat16 d_Ws [3 * DD * K3];
__device__ __half        d_Gs [GS_ROWS * KA3];
__device__ __half        d_Xs [(size_t)RR * KB3];
__device__ float         d_XFt[(size_t)MROWS * RR];
__device__ __half        d_OFsT[(size_t)KA5 * RR];       // stage-5 A, K-major [j, r]
__device__ __half        d_ITb[DD * KB5];

// ---------------- helpers ----------------
__device__ __forceinline__ uint32_t s2u(const void* p) {
    uint32_t a;
    asm("{ .reg .u64 t; cvta.to.shared.u64 t, %1; cvt.u32.u64 %0, t; }" : "=r"(a) : "l"(p));
    return a;
}
__device__ __forceinline__ uint32_t swz(uint32_t o) { return o ^ ((o >> 3) & 0x70); }
#define CP16(dst, src) asm volatile("cp.async.cg.shared.global [%0], [%1], 16;" :: "r"(dst), "l"(src))
#define CP_COMMIT()    asm volatile("cp.async.commit_group;" ::: "memory")
#define WG(n) asm volatile("cp.async.wait_group " #n ";" ::: "memory")

__device__ __forceinline__ uint32_t packh(__half a, __half b) {
    return (uint32_t)__half_as_ushort(a) | ((uint32_t)__half_as_ushort(b) << 16);
}
__device__ __forceinline__ uint32_t packsplit_h(float v0, float v1, uint32_t& lo) {
    __half h0 = __float2half(v0); __half l0 = __float2half(v0 - __half2float(h0));
    __half h1 = __float2half(v1); __half l1 = __float2half(v1 - __half2float(h1));
    lo = packh(l0, l1);
    return packh(h0, h1);
}
__device__ __forceinline__ void split2b(float v, __nv_bfloat16& h, __nv_bfloat16& l) {
    h = __float2bfloat16(v);
    l = __float2bfloat16(v - __bfloat162float(h));
}
__device__ __forceinline__ uint32_t packbf(__nv_bfloat16 a, __nv_bfloat16 b) {
    return (uint32_t)__bfloat16_as_ushort(a) | ((uint32_t)__bfloat16_as_ushort(b) << 16);
}
__device__ __forceinline__ uint32_t packsplit_b(float v0, float v1, uint32_t& lo) {
    __nv_bfloat16 h0, l0, h1, l1; split2b(v0, h0, l0); split2b(v1, h1, l1);
    lo = packbf(l0, l1);
    return packbf(h0, h1);
}

template <bool BF>
__device__ __forceinline__ void mma16816(float* d, const uint32_t* a, uint32_t b0, uint32_t b1) {
    if constexpr (BF)
        asm volatile(
            "mma.sync.aligned.m16n8k16.row.col.f32.bf16.bf16.f32 "
            "{%0,%1,%2,%3}, {%4,%5,%6,%7}, {%8,%9}, {%0,%1,%2,%3};"
            : "+f"(d[0]), "+f"(d[1]), "+f"(d[2]), "+f"(d[3])
            : "r"(a[0]), "r"(a[1]), "r"(a[2]), "r"(a[3]), "r"(b0), "r"(b1));
    else
        asm volatile(
            "mma.sync.aligned.m16n8k16.row.col.f32.f16.f16.f32 "
            "{%0,%1,%2,%3}, {%4,%5,%6,%7}, {%8,%9}, {%0,%1,%2,%3};"
            : "+f"(d[0]), "+f"(d[1]), "+f"(d[2]), "+f"(d[3])
            : "r"(a[0]), "r"(a[1]), "r"(a[2]), "r"(a[3]), "r"(b0), "r"(b1));
}

// ---------------- fused prep: TwS + ITb tables, W^T split, X convert ----------------
__global__ void prep_kernel(const float* __restrict__ x,
                            const float* __restrict__ Wk, const float* __restrict__ Wv,
                            const float* __restrict__ Wq) {
    const int idx = blockIdx.x * blockDim.x + threadIdx.x;
    const float w = 2.0f * CUDART_PI_F / (float)DD;

    if (idx < TWROWS * (DD / 2)) {
        int c = idx / (DD / 2), op = idx % (DD / 2);
        float v0 = 0.0f, v1 = 0.0f;
        if (c < 2 * FF) {
            int f = (c < FF) ? c : (c - FF);
            int r0 = (f * (2 * op)) % DD, r1 = (f * (2 * op + 1)) % DD;
            if (c < FF) { v0 = cosf(w * (float)r0);  v1 = cosf(w * (float)r1); }
            else        { v0 = -sinf(w * (float)r0); v1 = -sinf(w * (float)r1); }
        }
        uint32_t lp, hp = packsplit_b(v0, v1, lp);
        uint32_t* row = (uint32_t*)(d_TwS + (size_t)c * K3);
        row[op] = hp; row[DD / 2 + op] = lp; row[DD + op] = hp;     // (hi, lo, hi)
    }
    if (idx < DD * (KB5 / 2)) {
        int d = idx / (KB5 / 2), fp = idx % (KB5 / 2);
        float v0 = 0.0f, v1 = 0.0f;
        if (fp < FF) {
            int f = fp;
            bool edge = (f == 0) || (f == DD / 2);
            float c = edge ? (1.0f / DD) : (2.0f / DD);
            int r = (f * d) % DD;
            float ang = w * (float)r;
            v0 = c * cosf(ang);
            v1 = edge ? 0.0f : -c * sinf(ang);
        }
        uint32_t* row = (uint32_t*)(d_ITb + (size_t)d * KB5);
        row[fp] = packh(__float2half(v0), __float2half(v1));
    }
    if (idx < 3 * (DD / 2) * DD) {
        int z = idx / ((DD / 2) * DD);
        int rem = idx % ((DD / 2) * DD);
        int op = rem / DD, in = rem % DD;
        const float* W = (z == 0) ? Wk : (z == 1) ? Wv : Wq;
        float v0 = W[(size_t)(2 * op) * DD + in];
        float v1 = W[(size_t)(2 * op + 1) * DD + in];
        uint32_t lp, hp = packsplit_b(v0, v1, lp);
        uint32_t* row = (uint32_t*)(d_Ws + (size_t)(z * DD + in) * K3);
        row[op] = hp; row[DD / 2 + op] = hp; row[DD + op] = lp;     // (hi, hi, lo)
    }
    if (idx < RR * DD / 2) {
        int r = idx / (DD / 2), cp = idx % (DD / 2);
        float2 v = *(const float2*)&x[(size_t)r * DD + cp * 2];
        ((uint32_t*)(d_Xs + (size_t)r * KB3))[cp] = packh(__float2half(v.x), __float2half(v.y));
    }
}

// ---------------- HMMA GEMM: C[m,n] = sum_k A[m,k]*B[n,k] ----------------
// R8-proven loop: CTA tile 128xNT, 8 warps (2m x 4n), BK=64, 4-stage interleaved
// ring (A+B per stage), single barrier per chunk, B chunk wraps at BPER.
// ATRANS=1: A is K-major [k, m]; A fragments via ldmatrix.trans.
// MODE 0: fp32 C.  MODE 1: C = resid + gain[0]*4096*acc.
// MODE 2 (fold, bf16): fp16 hi-only store into d_Gs (+z slot), masked col<SLOT.
template <int MODE, int NT, int ATRANS>
__global__ __launch_bounds__(256, 1) void hmma_gemm(
    int NKT, int BPER,
    const __nv_bfloat16* __restrict__ A, int lda,
    const __nv_bfloat16* __restrict__ B, int ldb,
    float* __restrict__ C, int ldc,
    const float* __restrict__ resid, const float* __restrict__ gain)
{
    constexpr int NFR = NT / 32;
    constexpr uint32_t ASZ = 16384u;
    constexpr uint32_t BSZ = (uint32_t)NT * 128u;
    constexpr uint32_t STG = ASZ + BSZ;

    extern __shared__ char smraw[];
    const uint32_t sbase = (s2u(smraw) + 1023u) & ~1023u;
    const int t = threadIdx.x;
    const int lane = t & 31, w = t >> 5;
    const int wm = w >> 2, wn = w & 3;
    const int m0 = blockIdx.x * 128, n0 = blockIdx.y * NT;
    if (MODE == 2) B += (size_t)blockIdx.z * DD * ldb;

    float acc[4][NFR][4];
#pragma unroll
    for (int i = 0; i < 4; i++)
#pragma unroll
        for (int j = 0; j < NFR; j++)
#pragma unroll
            for (int q = 0; q < 4; q++) acc[i][j][q] = 0.0f;

    const int arow = wm * 64 + (lane & 15);
    const int akoff = (lane >> 4) * 16;
    const int tkrow = (lane & 7) + ((lane >> 4) * 8);
    const int tcolb = ((lane >> 3) & 1) * 16;
    const int brow0 = (lane & 7) + ((lane >> 4) * 8);
    const int bkoff = ((lane >> 3) & 1) * 16;

    auto issue = [&](int kt) {
        const uint32_t sA = sbase + (uint32_t)(kt & 3) * STG;
        const uint32_t sB = sA + ASZ;
        const int bkt = kt % BPER;
        if (ATRANS) {
#pragma unroll
            for (int i = 0; i < 4; i++) {
                const int s = t + i * 256;
                const int j = s >> 4, rseg = s & 15;
                const int smrow = j * 2 + (rseg >> 3);
                CP16(sA + swz((uint32_t)(smrow * 128 + (rseg & 7) * 16)),
                     (const char*)A + ((size_t)(kt * 64 + j) * lda + m0 + rseg * 8) * 2);
            }
        } else {
#pragma unroll
            for (int i = 0; i < 4; i++) {
                const int s = t + i * 256, row = s >> 3, c = s & 7;
                CP16(sA + swz((uint32_t)(row * 128 + c * 16)),
                     (const char*)A + ((size_t)(m0 + row) * lda + kt * 64 + c * 8) * 2);
            }
        }
#pragma unroll
        for (int i = 0; i < NT / 32; i++) {
            const int s = t + i * 256, row = s >> 3, c = s & 7;
            CP16(sB + swz((uint32_t)(row * 128 + c * 16)),
                 (const char*)B + ((size_t)(n0 + row) * ldb + bkt * 64 + c * 8) * 2);
        }
        CP_COMMIT();
    };

    issue(0);
    if (NKT > 1) issue(1);
    if (NKT > 2) issue(2);
    for (int kt = 0; kt < NKT; kt++) {
        const int rem = NKT - kt - 1;
        if (rem >= 2)      { WG(2); }
        else if (rem == 1) { WG(1); }
        else               { WG(0); }
        __syncthreads();
        if (kt + 3 < NKT) issue(kt + 3);

        const uint32_t sA = sbase + (uint32_t)(kt & 3) * STG;
        const uint32_t sB = sA + ASZ;
#pragma unroll
        for (int k16 = 0; k16 < 4; k16++) {
            uint32_t a[4][4];
            if (ATRANS) {
#pragma unroll
                for (int mf = 0; mf < 4; mf++) {
                    const int smrow = (k16 * 16 + tkrow) * 2 + wm;
                    uint32_t addr = sA + swz((uint32_t)(smrow * 128 + mf * 32 + tcolb));
                    asm volatile("ldmatrix.sync.aligned.m8n8.x4.trans.shared.b16 {%0,%1,%2,%3}, [%4];"
                        : "=r"(a[mf][0]), "=r"(a[mf][1]), "=r"(a[mf][2]), "=r"(a[mf][3]) : "r"(addr));
                }
            } else {
#pragma unroll
                for (int mf = 0; mf < 4; mf++) {
                    uint32_t addr = sA + swz((uint32_t)((arow + mf * 16) * 128 + k16 * 32 + akoff));
                    asm volatile("ldmatrix.sync.aligned.m8n8.x4.shared.b16 {%0,%1,%2,%3}, [%4];"
                        : "=r"(a[mf][0]), "=r"(a[mf][1]), "=r"(a[mf][2]), "=r"(a[mf][3]) : "r"(addr));
                }
            }
#pragma unroll
            for (int p = 0; p < NT / 64; p++) {
                uint32_t q0, q1, q2, q3;
                uint32_t addr = sB + swz((uint32_t)((wn * (NT / 4) + p * 16 + brow0) * 128 + k16 * 32 + bkoff));
                asm volatile("ldmatrix.sync.aligned.m8n8.x4.shared.b16 {%0,%1,%2,%3}, [%4];"
                    : "=r"(q0), "=r"(q1), "=r"(q2), "=r"(q3) : "r"(addr));
#pragma unroll
                for (int mf = 0; mf < 4; mf++) {
                    mma16816<MODE == 2>(acc[mf][2 * p], a[mf], q0, q1);
                    mma16816<MODE == 2>(acc[mf][2 * p + 1], a[mf], q2, q3);
                }
            }
        }
    }

    // ---------------- epilogue ----------------
    const int r = lane >> 2, c2 = (lane & 3) * 2;
    if (MODE == 2) {
        __half* gbase = d_Gs + (size_t)blockIdx.z * SLOT * KA3;
#pragma unroll
        for (int mf = 0; mf < 4; mf++) {
#pragma unroll
            for (int nf = 0; nf < NFR; nf++) {
                const int ml = m0 + wm * 64 + mf * 16 + r;
                const int n = n0 + wn * (NT / 4) + nf * 8 + c2;
#pragma unroll
                for (int hh = 0; hh < 2; hh++) {
                    const int mrow = ml + hh * 8;
                    if (mrow < SLOT) {
                        // hi-only store (stage-3 is 1-term fp16)
                        uint32_t hp = packh(__float2half(acc[mf][nf][2 * hh]),
                                            __float2half(acc[mf][nf][2 * hh + 1]));
                        ((uint32_t*)(gbase + (size_t)mrow * KA3))[n / 2] = hp;
                    }
                }
            }
        }
        return;
    }
    const float g = (MODE == 1) ? gain[0] * ISCALE5 : 0.0f;
#pragma unroll
    for (int mf = 0; mf < 4; mf++) {
#pragma unroll
        for (int nf = 0; nf < NFR; nf++) {
            const int m = m0 + wm * 64 + mf * 16 + r;
            const int n = n0 + wn * (NT / 4) + nf * 8 + c2;
            const size_t o0 = (size_t)m * ldc + n;
            const size_t o1 = (size_t)(m + 8) * ldc + n;
            if (MODE == 1) {
                float2 x0 = *(const float2*)&resid[o0];
                float2 x1 = *(const float2*)&resid[o1];
                *(float2*)&C[o0] = make_float2(x0.x + g * acc[mf][nf][0], x0.y + g * acc[mf][nf][1]);
                *(float2*)&C[o1] = make_float2(x1.x + g * acc[mf][nf][2], x1.y + g * acc[mf][nf][3]);
            } else {
                *(float2*)&C[o0] = make_float2(acc[mf][nf][0], acc[mf][nf][1]);
                *(float2*)&C[o1] = make_float2(acc[mf][nf][2], acc[mf][nf][3]);
            }
        }
    }
}

// ---------------- causal scan: coalesced K-major fp16-split output ----------------
__global__ __launch_bounds__(512) void scan_kernel() {
    const int f = blockIdx.x;
    const int b = blockIdx.y;
    const int base = b * SS;
    const int t = threadIdx.x;
    const int lane = t & 31, wid = t >> 5;
    const int s0 = t * 8;

    const float* kre = d_XFt + (size_t)(0 * SLOT + f)      * RR + base;
    const float* kim = d_XFt + (size_t)(0 * SLOT + FF + f) * RR + base;
    const float* vre = d_XFt + (size_t)(1 * SLOT + f)      * RR + base;
    const float* vim = d_XFt + (size_t)(1 * SLOT + FF + f) * RR + base;
    const float* qre = d_XFt + (size_t)(2 * SLOT + f)      * RR + base;
    const float* qim = d_XFt + (size_t)(2 * SLOT + FF + f) * RR + base;

    float kr[8], ki[8], vr[8], vi[8], qr[8], qi[8];
#pragma unroll
    for (int h = 0; h < 2; h++) {
        *(float4*)(kr + 4 * h) = *(const float4*)(kre + s0 + 4 * h);
        *(float4*)(ki + 4 * h) = *(const float4*)(kim + s0 + 4 * h);
        *(float4*)(vr + 4 * h) = *(const float4*)(vre + s0 + 4 * h);
        *(float4*)(vi + 4 * h) = *(const float4*)(vim + s0 + 4 * h);
        *(float4*)(qr + 4 * h) = *(const float4*)(qre + s0 + 4 * h);
        *(float4*)(qi + 4 * h) = *(const float4*)(qim + s0 + 4 * h);
    }

    float lr[8], li[8], runr = 0.0f, runi = 0.0f;
#pragma unroll
    for (int i = 0; i < 8; i++) {
        float zr = kr[i] * vr[i] - ki[i] * vi[i];
        float zi = kr[i] * vi[i] + ki[i] * vr[i];
        runr += zr; runi += zi;
        lr[i] = runr; li[i] = runi;
    }

    float wr = runr, wi = runi;
#pragma unroll
    for (int off = 1; off < 32; off <<= 1) {
        float pr = __shfl_up_sync(0xFFFFFFFFu, wr, off);
        float pi = __shfl_up_sync(0xFFFFFFFFu, wi, off);
        if (lane >= off) { wr += pr; wi += pi; }
    }
    __shared__ float swr[16], swi[16];
    if (lane == 31) { swr[wid] = wr; swi[wid] = wi; }
    __syncthreads();
    if (t < 32) {
        float vr2 = (t < 16) ? swr[t] : 0.0f;
        float vi2 = (t < 16) ? swi[t] : 0.0f;
#pragma unroll
        for (int off = 1; off < 16; off <<= 1) {
            float pr = __shfl_up_sync(0xFFFFFFFFu, vr2, off);
            float pi = __shfl_up_sync(0xFFFFFFFFu, vi2, off);
            if (lane >= off) { vr2 += pr; vi2 += pi; }
        }
        if (t < 16) { swr[t] = vr2; swi[t] = vi2; }
    }
    __syncthreads();
    const float baser = (wid > 0) ? swr[wid - 1] : 0.0f;
    const float basei = (wid > 0) ? swi[wid - 1] : 0.0f;
    const float exr = baser + (wr - runr);
    const float exi = basei + (wi - runi);

    uint32_t hx[4], lx[4], hy[4], ly[4];
#pragma unroll
    for (int i = 0; i < 4; i++) {
        float o0x, o0y, o1x, o1y;
        {
            float mr = exr + lr[2 * i],     mi = exi + li[2 * i];
            o0x = (mr * qr[2 * i] + mi * qi[2 * i]) * SCALE5;
            o0y = (mi * qr[2 * i] - mr * qi[2 * i]) * SCALE5;
        }
        {
            float mr = exr + lr[2 * i + 1], mi = exi + li[2 * i + 1];
            o1x = (mr * qr[2 * i + 1] + mi * qi[2 * i + 1]) * SCALE5;
            o1y = (mi * qr[2 * i + 1] - mr * qi[2 * i + 1]) * SCALE5;
        }
        uint32_t l0; hx[i] = packsplit_h(o0x, o1x, l0); lx[i] = l0;
        uint32_t l1; hy[i] = packsplit_h(o0y, o1y, l1); ly[i] = l1;
    }
    const size_t col = (size_t)base + s0;
    *(uint4*)&d_OFsT[(size_t)(2 * f)           * RR + col] = make_uint4(hx[0], hx[1], hx[2], hx[3]);
    *(uint4*)&d_OFsT[(size_t)(2 * f + 1)       * RR + col] = make_uint4(hy[0], hy[1], hy[2], hy[3]);
    *(uint4*)&d_OFsT[(size_t)(KB5 + 2 * f)     * RR + col] = make_uint4(lx[0], lx[1], lx[2], lx[3]);
    *(uint4*)&d_OFsT[(size_t)(KB5 + 2 * f + 1) * RR + col] = make_uint4(ly[0], ly[1], ly[2], ly[3]);
}

// ---------------- launch ----------------
#define SMEM_256 (4 * (16384 + 256 * 128) + 1024)
#define SMEM_128 (4 * (16384 + 128 * 128) + 1024)
extern "C" void kernel_launch(void* const* d_in, const int* in_sizes, int n_in,
                              void* d_out, int out_size) {
    const float* x    = (const float*)d_in[0];
    const float* Wk   = (const float*)d_in[1];
    const float* Wv   = (const float*)d_in[2];
    const float* Wq   = (const float*)d_in[3];
    const float* gain = (const float*)d_in[4];
    float* out = (float*)d_out;

    void *pTwS, *pWs, *pGs, *pXs, *pOFsT, *pITb, *pXFt;
    cudaGetSymbolAddress(&pTwS, d_TwS);
    cudaGetSymbolAddress(&pWs,  d_Ws);
    cudaGetSymbolAddress(&pGs,  d_Gs);
    cudaGetSymbolAddress(&pXs,  d_Xs);
    cudaGetSymbolAddress(&pOFsT, d_OFsT);
    cudaGetSymbolAddress(&pITb, d_ITb);
    cudaGetSymbolAddress(&pXFt, d_XFt);

    cudaFuncSetAttribute((const void*)hmma_gemm<0, 256, 0>, cudaFuncAttributeMaxDynamicSharedMemorySize, SMEM_256);
    cudaFuncSetAttribute((const void*)hmma_gemm<1, 256, 1>, cudaFuncAttributeMaxDynamicSharedMemorySize, SMEM_256);
    cudaFuncSetAttribute((const void*)hmma_gemm<2, 128, 0>, cudaFuncAttributeMaxDynamicSharedMemorySize, SMEM_128);

    // 0) fused prep: tables + W split + X convert
    prep_kernel<<<(RR * DD / 2 + 255) / 256, 256>>>(x, Wk, Wv, Wq);

    // 1) fold GEMM (bf16 3-term, NT=128, fp16 hi-only store into Gs)
    hmma_gemm<2, 128, 0><<<dim3(TWROWS / 128, DD / 128, 3), 256, SMEM_128>>>(
        K3 / 64, K3 / 64,
        (const __nv_bfloat16*)pTwS, K3, (const __nv_bfloat16*)pWs, K3,
        nullptr, 0, nullptr, nullptr);

    // 2) stage-3 GEMM (fp16 1-term): XFt[col, r]  M=2432, N=16384, K=768
    hmma_gemm<0, 256, 0><<<dim3(MROWS / 128, RR / 256), 256, SMEM_256>>>(
        KA3 / 64, KA3 / 64,
        (const __nv_bfloat16*)pGs, KA3, (const __nv_bfloat16*)pXs, KB3,
        (float*)pXFt, RR, nullptr, nullptr);

    // 3) causal scan -> OFsT (K-major, coalesced fp16 split + prescale)
    scan_kernel<<<dim3(FF, BB), 512>>>();

    // 4) stage-5 GEMM + residual (fp16 2-term, A K-major via ldmatrix.trans):
    //    out[r,d]  M=16384, N=768, K=1664 (B period 832)
    hmma_gemm<1, 256, 1><<<dim3(RR / 128, DD / 256), 256, SMEM_256>>>(
        KA5 / 64, KB5 / 64,
        (const __nv_bfloat16*)pOFsT, RR, (const __nv_bfloat16*)pITb, KB5,
        out, DD, x, gain);
}